// round 16
// baseline (speedup 1.0000x reference)
#include <cuda_runtime.h>
#include <cuda_fp16.h>
#include <stdint.h>

// Conv2d 3x3 s1 p1: x(32,128,56,56) f32, w(256,128,3,3) f32 -> out(32,256,56,56) f32
// Implicit GEMM, single-pass fp16 mma.sync.m16n8k16 (fp32 accumulate).
// R16 = R14 pairing (tile M256xN128, 512 thr, BK=32, ring-6, 1 barrier / 2 stages)
// + SAFE cross-barrier fragment prefetch: WAITG(1) BEFORE the barrier publishes
//   stage s+2 to all threads, so the end-of-iteration ldsm prefetch reads only
//   barrier-published smem (fixes R15's cross-thread cp.async race).

#define N_IMG   32
#define C_IN    128
#define HWD     56
#define PIX     3136
#define C_OUT   256
#define M_TOTAL 100352
#define KTOT    1152
#define BK      32
#define NSTAGE  (KTOT / BK)     // 36
#define RING    6
#define MT      256
#define NT      128

#define XBLOCKS (N_IMG * 98)                          // 3136
#define WELEMS  (NSTAGE * C_OUT * BK)                 // 294912
#define WBLOCKS ((WELEMS + 255) / 256)                // 1152

// -------- device scratch (no allocation allowed) --------
__device__ __half g_x[(size_t)N_IMG * PIX * C_IN];            // NHWC fp16
__device__ __half g_wst[(size_t)NSTAGE * C_OUT * BK];         // stage-major: [s][oc][32]

// ==================== fused prep: x NCHW f32 -> NHWC fp16 | w -> stage-major fp16 ====
__global__ void prep_all(const float* __restrict__ x, const float* __restrict__ w) {
    if (blockIdx.x < XBLOCKS) {
        __shared__ uint16_t sh[128 * 33];
        int n  = blockIdx.x / 98;
        int pt = blockIdx.x - n * 98;
        int p0 = pt * 32;
        int t = threadIdx.x;
        int lane = t & 31;
        #pragma unroll
        for (int i = 0; i < 16; i++) {
            int c = (t >> 5) + 8 * i;
            float v = x[((size_t)n * 128 + c) * PIX + p0 + lane];
            sh[c * 33 + lane] = __half_as_ushort(__float2half_rn(v));
        }
        __syncthreads();
        int c4 = lane * 4;
        #pragma unroll
        for (int i = 0; i < 4; i++) {
            int pix = (t >> 5) + 8 * i;
            size_t base = ((size_t)n * PIX + p0 + pix) * 128 + c4;
            uint2 vh;
            vh.x = (uint32_t)sh[(c4 + 0) * 33 + pix] | ((uint32_t)sh[(c4 + 1) * 33 + pix] << 16);
            vh.y = (uint32_t)sh[(c4 + 2) * 33 + pix] | ((uint32_t)sh[(c4 + 3) * 33 + pix] << 16);
            *reinterpret_cast<uint2*>(&g_x[base]) = vh;
        }
    } else {
        int idx = (blockIdx.x - XBLOCKS) * 256 + threadIdx.x;
        if (idx >= WELEMS) return;
        int i  = idx & 31;
        int oc = (idx >> 5) & 255;
        int s  = idx >> 13;
        int k  = s * BK + i;
        int tap = k >> 7;
        int c   = k & 127;
        g_wst[idx] = __float2half_rn(w[(size_t)oc * KTOT + c * 9 + tap]);
    }
}

// ==================== main kernel ====================
// stage: A[256 rows][80B] @0 (20480B), B[128 rows][80B] @20480 (10240B)
//        -> 30720B/stage, RING=6 -> 184320B, 1 CTA(512thr)/SM, 16 warps/SM
#define ROWB   80
#define A_OFF  0
#define B_OFF  (256 * ROWB)
#define STG_B  (256 * ROWB + 128 * ROWB)
#define SMEMSZ (RING * STG_B)

__device__ __forceinline__ uint32_t smem_u32(const void* p) {
    uint32_t a;
    asm("{ .reg .u64 t; cvta.to.shared.u64 t, %1; cvt.u32.u64 %0, t; }" : "=r"(a) : "l"(p));
    return a;
}
#define CP16(dst, src, sz) \
    asm volatile("cp.async.ca.shared.global [%0], [%1], 16, %2;" \
                 :: "r"(dst), "l"(src), "r"(sz) : "memory")
#define CP_COMMIT()  asm volatile("cp.async.commit_group;" ::: "memory")
#define CP_WAITG(n)  asm volatile("cp.async.wait_group %0;" :: "n"(n) : "memory")

__device__ __forceinline__ void ldsm_x4(uint32_t* r, uint32_t addr) {
    asm volatile("ldmatrix.sync.aligned.m8n8.x4.shared.b16 {%0,%1,%2,%3}, [%4];"
                 : "=r"(r[0]), "=r"(r[1]), "=r"(r[2]), "=r"(r[3]) : "r"(addr));
}
__device__ __forceinline__ void mma16816(float* c, const uint32_t* a, const uint32_t* b) {
    asm volatile(
        "mma.sync.aligned.m16n8k16.row.col.f32.f16.f16.f32 "
        "{%0,%1,%2,%3}, {%4,%5,%6,%7}, {%8,%9}, {%0,%1,%2,%3};"
        : "+f"(c[0]), "+f"(c[1]), "+f"(c[2]), "+f"(c[3])
        : "r"(a[0]), "r"(a[1]), "r"(a[2]), "r"(a[3]), "r"(b[0]), "r"(b[1]));
}

__global__ __launch_bounds__(512, 1)
void conv_mma(float* __restrict__ out) {
    extern __shared__ __align__(128) char smem[];
    const uint32_t sb = smem_u32(smem);

    const int t   = threadIdx.x;
    const int lid = t & 31;
    const int wid = t >> 5;            // 0..15
    const int bm0 = blockIdx.x * MT;
    const int oc0 = blockIdx.y * NT;

    // ---- loader roles: A: 2 threads/row (2 CP16 each); B: 4 threads/row (1 CP16) ----
    const int arow = t >> 1;           // 0..255
    const int aoff = (t & 1) * 32;
    const int brow = t >> 2;           // 0..127
    const int boff = (t & 3) * 16;
    const char* wbase = (const char*)g_wst;

    // per-thread A-row coordinates
    const int p    = bm0 + arow;
    const int n    = p / PIX;
    const int prem = p - n * PIX;
    const int oh   = prem / HWD;
    const int ow   = prem - oh * HWD;
    const char* xbase = (const char*)g_x + (size_t)n * PIX * 256;

    // ---- compute mapping: 4x4 warps, warp tile 64x32 ----
    const int m_base = (wid >> 2) * 64;
    const int n_base = (wid & 3) * 32;
    const int j   = lid >> 3;
    const int rin = lid & 7;
    const int a_lane = ((j & 1) * 8 + rin) * ROWB + (j >> 1) * 16;
    const int b_lane = ((j >> 1) * 8 + rin) * ROWB + (j & 1) * 16;
    const int erow = lid >> 2;
    const int ecol = (lid & 3) * 2;

    float acc[4][4][4];
    #pragma unroll
    for (int i = 0; i < 4; i++)
        #pragma unroll
        for (int jj = 0; jj < 4; jj++)
            #pragma unroll
            for (int q = 0; q < 4; q++) acc[i][jj][q] = 0.0f;

    // prefetched kk0 fragments for the next pair's first stage
    uint32_t Fa[4][4], Fb[2][4];

    auto issue = [&](int s, int slot) {
        const uint32_t stg = sb + slot * STG_B;
        const int tap = s >> 2;
        const int c0  = (s & 3) * 32;
        const int dh = tap / 3 - 1, dw = tap % 3 - 1;
        const int ih = oh + dh, iw = ow + dw;
        const bool v = ((unsigned)ih < (unsigned)HWD) && ((unsigned)iw < (unsigned)HWD);
        const uint32_t vsz = v ? 16u : 0u;
        const char* asrc = xbase + ((size_t)(v ? ih * HWD + iw : 0) * 128 + c0) * 2 + aoff;
        const uint32_t adst = stg + A_OFF + arow * ROWB + aoff;
        CP16(adst,      asrc,      vsz);
        CP16(adst + 16, asrc + 16, vsz);
        const char* bsrc = wbase + ((size_t)(s * C_OUT + oc0 + brow) * BK) * 2 + boff;
        const uint32_t bdst = stg + B_OFF + brow * ROWB + boff;
        CP16(bdst, bsrc, 16u);
        CP_COMMIT();
    };

    auto prefetch_F = [&](int slot) {
        const uint32_t stg = sb + slot * STG_B;
        const uint32_t abase = stg + A_OFF + m_base * ROWB + a_lane;
        const uint32_t bbase = stg + B_OFF + n_base * ROWB + b_lane;
        #pragma unroll
        for (int mt = 0; mt < 4; mt++) ldsm_x4(Fa[mt], abase + mt * (16 * ROWB));
        #pragma unroll
        for (int nt = 0; nt < 2; nt++) ldsm_x4(Fb[nt], bbase + nt * (16 * ROWB));
    };

    // first stage of a pair: kk0 from prefetched F, kk1 from smem
    auto compute_first = [&](int slot) {
        #pragma unroll
        for (int mt = 0; mt < 4; mt++)
            #pragma unroll
            for (int n8 = 0; n8 < 4; n8++)
                mma16816(acc[mt][n8], Fa[mt], &Fb[n8 >> 1][(n8 & 1) * 2]);
        const uint32_t stg = sb + slot * STG_B;
        const uint32_t abase = stg + A_OFF + m_base * ROWB + a_lane;
        const uint32_t bbase = stg + B_OFF + n_base * ROWB + b_lane;
        uint32_t ah[4][4], bh[2][4];
        #pragma unroll
        for (int mt = 0; mt < 4; mt++)
            ldsm_x4(ah[mt], abase + mt * (16 * ROWB) + 32);
        #pragma unroll
        for (int nt = 0; nt < 2; nt++)
            ldsm_x4(bh[nt], bbase + nt * (16 * ROWB) + 32);
        #pragma unroll
        for (int mt = 0; mt < 4; mt++)
            #pragma unroll
            for (int n8 = 0; n8 < 4; n8++)
                mma16816(acc[mt][n8], ah[mt], &bh[n8 >> 1][(n8 & 1) * 2]);
    };

    auto compute = [&](int slot) {
        const uint32_t stg = sb + slot * STG_B;
        const uint32_t abase = stg + A_OFF + m_base * ROWB + a_lane;
        const uint32_t bbase = stg + B_OFF + n_base * ROWB + b_lane;
        #pragma unroll
        for (int kk = 0; kk < 2; kk++) {
            uint32_t ah[4][4], bh[2][4];
            #pragma unroll
            for (int mt = 0; mt < 4; mt++)
                ldsm_x4(ah[mt], abase + mt * (16 * ROWB) + kk * 32);
            #pragma unroll
            for (int nt = 0; nt < 2; nt++)
                ldsm_x4(bh[nt], bbase + nt * (16 * ROWB) + kk * 32);
            #pragma unroll
            for (int mt = 0; mt < 4; mt++)
                #pragma unroll
                for (int n8 = 0; n8 < 4; n8++)
                    mma16816(acc[mt][n8], ah[mt], &bh[n8 >> 1][(n8 & 1) * 2]);
        }
    };

    // prologue: stages 0..3 into slots 0..3; publish stage 0; prefetch F(stage 0)
    issue(0, 0); issue(1, 1); issue(2, 2); issue(3, 3);
    CP_WAITG(1);            // stages <= 2 done in-thread
    __syncthreads();        // published to all threads
    prefetch_F(0);          // safe: stage 0 is barrier-published

    // paired stages; slot pattern period 6 = ring size; 1 barrier per 2 stages.
    // WAITG(1) BEFORE the barrier => stages <= s+2 are barrier-published, making
    // the end-of-iteration prefetch of stage s+2 race-free.
    #pragma unroll 1
    for (int gg = 0; gg < 6; ++gg) {
        #pragma unroll
        for (int pp = 0; pp < 3; ++pp) {
            const int s = gg * 6 + pp * 2;
            if (s + 4 < NSTAGE) CP_WAITG(1);
            else                CP_WAITG(0);
            __syncthreads();
            // slot(s+4) == slot(s-2): all its readers (computes at iter s-2,
            // prefetch at iter s-4) are before the barrier above
            if (s + 4 < NSTAGE) issue(s + 4, (pp * 2 + 4) % 6);
            if (s + 5 < NSTAGE) issue(s + 5, (pp * 2 + 5) % 6);
            compute_first(pp * 2);      // kk0 issues immediately from F
            compute(pp * 2 + 1);
            if (s + 2 < NSTAGE) prefetch_F((pp * 2 + 2) % 6);   // barrier-published
        }
    }

    // ---- epilogue: NCHW stores ----
    #pragma unroll
    for (int mt = 0; mt < 4; mt++) {
        #pragma unroll
        for (int half = 0; half < 2; half++) {
            const int pix = bm0 + m_base + mt * 16 + erow + half * 8;
            const int nn  = pix / PIX;
            const int pr  = pix - nn * PIX;
            float* ob = out + (size_t)nn * C_OUT * PIX + pr;
            #pragma unroll
            for (int n8 = 0; n8 < 4; n8++) {
                const int oc = oc0 + n_base + n8 * 8 + ecol;
                ob[(size_t)oc * PIX]       = acc[mt][n8][half * 2];
                ob[(size_t)(oc + 1) * PIX] = acc[mt][n8][half * 2 + 1];
            }
        }
    }
}

// ==================== launch ====================
extern "C" void kernel_launch(void* const* d_in, const int* in_sizes, int n_in,
                              void* d_out, int out_size) {
    const float* x = (const float*)d_in[0];
    const float* w = (const float*)d_in[1];
    float* out = (float*)d_out;

    static int smem_set = 0;
    if (!smem_set) {
        cudaFuncSetAttribute(conv_mma, cudaFuncAttributeMaxDynamicSharedMemorySize, SMEMSZ);
        smem_set = 1;
    }

    prep_all<<<XBLOCKS + WBLOCKS, 256>>>(x, w);
    dim3 grid(M_TOTAL / MT, C_OUT / NT);   // (392, 2)
    conv_mma<<<grid, 512, SMEMSZ>>>(out);
}

// round 17
// speedup vs baseline: 1.1439x; 1.1439x over previous
#include <cuda_runtime.h>
#include <cuda_fp16.h>
#include <stdint.h>

// Conv2d 3x3 s1 p1: x(32,128,56,56) f32, w(256,128,3,3) f32 -> out(32,256,56,56) f32
// Implicit GEMM, single-pass fp16 mma.sync.m16n8k16 (fp32 accumulate).
// R17 = R14 winner (tile M256xN128, 512 thr, BK=32, ring-6, 1 barrier / 2 stages)
// + post-barrier reorder: the first stage's kk0 ldmatrix batch is hoisted ahead
//   of the cp.async issue calls, shortening the cold-start convoy at each of the
//   18 barrier epochs. No sync/arithmetic changes vs R14.

#define N_IMG   32
#define C_IN    128
#define HWD     56
#define PIX     3136
#define C_OUT   256
#define M_TOTAL 100352
#define KTOT    1152
#define BK      32
#define NSTAGE  (KTOT / BK)     // 36
#define RING    6
#define MT      256
#define NT      128

#define XBLOCKS (N_IMG * 98)                          // 3136
#define WELEMS  (NSTAGE * C_OUT * BK)                 // 294912
#define WBLOCKS ((WELEMS + 255) / 256)                // 1152

// -------- device scratch (no allocation allowed) --------
__device__ __half g_x[(size_t)N_IMG * PIX * C_IN];            // NHWC fp16
__device__ __half g_wst[(size_t)NSTAGE * C_OUT * BK];         // stage-major: [s][oc][32]

// ==================== fused prep: x NCHW f32 -> NHWC fp16 | w -> stage-major fp16 ====
__global__ void prep_all(const float* __restrict__ x, const float* __restrict__ w) {
    if (blockIdx.x < XBLOCKS) {
        __shared__ uint16_t sh[128 * 33];
        int n  = blockIdx.x / 98;
        int pt = blockIdx.x - n * 98;
        int p0 = pt * 32;
        int t = threadIdx.x;
        int lane = t & 31;
        #pragma unroll
        for (int i = 0; i < 16; i++) {
            int c = (t >> 5) + 8 * i;
            float v = x[((size_t)n * 128 + c) * PIX + p0 + lane];
            sh[c * 33 + lane] = __half_as_ushort(__float2half_rn(v));
        }
        __syncthreads();
        int c4 = lane * 4;
        #pragma unroll
        for (int i = 0; i < 4; i++) {
            int pix = (t >> 5) + 8 * i;
            size_t base = ((size_t)n * PIX + p0 + pix) * 128 + c4;
            uint2 vh;
            vh.x = (uint32_t)sh[(c4 + 0) * 33 + pix] | ((uint32_t)sh[(c4 + 1) * 33 + pix] << 16);
            vh.y = (uint32_t)sh[(c4 + 2) * 33 + pix] | ((uint32_t)sh[(c4 + 3) * 33 + pix] << 16);
            *reinterpret_cast<uint2*>(&g_x[base]) = vh;
        }
    } else {
        int idx = (blockIdx.x - XBLOCKS) * 256 + threadIdx.x;
        if (idx >= WELEMS) return;
        int i  = idx & 31;
        int oc = (idx >> 5) & 255;
        int s  = idx >> 13;
        int k  = s * BK + i;
        int tap = k >> 7;
        int c   = k & 127;
        g_wst[idx] = __float2half_rn(w[(size_t)oc * KTOT + c * 9 + tap]);
    }
}

// ==================== main kernel ====================
// stage: A[256 rows][80B] @0 (20480B), B[128 rows][80B] @20480 (10240B)
//        -> 30720B/stage, RING=6 -> 184320B, 1 CTA(512thr)/SM, 16 warps/SM
#define ROWB   80
#define A_OFF  0
#define B_OFF  (256 * ROWB)
#define STG_B  (256 * ROWB + 128 * ROWB)
#define SMEMSZ (RING * STG_B)

__device__ __forceinline__ uint32_t smem_u32(const void* p) {
    uint32_t a;
    asm("{ .reg .u64 t; cvta.to.shared.u64 t, %1; cvt.u32.u64 %0, t; }" : "=r"(a) : "l"(p));
    return a;
}
#define CP16(dst, src, sz) \
    asm volatile("cp.async.ca.shared.global [%0], [%1], 16, %2;" \
                 :: "r"(dst), "l"(src), "r"(sz) : "memory")
#define CP_COMMIT()  asm volatile("cp.async.commit_group;" ::: "memory")
#define CP_WAITG(n)  asm volatile("cp.async.wait_group %0;" :: "n"(n) : "memory")

__device__ __forceinline__ void ldsm_x4(uint32_t* r, uint32_t addr) {
    asm volatile("ldmatrix.sync.aligned.m8n8.x4.shared.b16 {%0,%1,%2,%3}, [%4];"
                 : "=r"(r[0]), "=r"(r[1]), "=r"(r[2]), "=r"(r[3]) : "r"(addr));
}
__device__ __forceinline__ void mma16816(float* c, const uint32_t* a, const uint32_t* b) {
    asm volatile(
        "mma.sync.aligned.m16n8k16.row.col.f32.f16.f16.f32 "
        "{%0,%1,%2,%3}, {%4,%5,%6,%7}, {%8,%9}, {%0,%1,%2,%3};"
        : "+f"(c[0]), "+f"(c[1]), "+f"(c[2]), "+f"(c[3])
        : "r"(a[0]), "r"(a[1]), "r"(a[2]), "r"(a[3]), "r"(b[0]), "r"(b[1]));
}

__global__ __launch_bounds__(512, 1)
void conv_mma(float* __restrict__ out) {
    extern __shared__ __align__(128) char smem[];
    const uint32_t sb = smem_u32(smem);

    const int t   = threadIdx.x;
    const int lid = t & 31;
    const int wid = t >> 5;            // 0..15
    const int bm0 = blockIdx.x * MT;
    const int oc0 = blockIdx.y * NT;

    // ---- loader roles: A: 2 threads/row (2 CP16 each); B: 4 threads/row (1 CP16) ----
    const int arow = t >> 1;           // 0..255
    const int aoff = (t & 1) * 32;
    const int brow = t >> 2;           // 0..127
    const int boff = (t & 3) * 16;
    const char* wbase = (const char*)g_wst;

    // per-thread A-row coordinates
    const int p    = bm0 + arow;
    const int n    = p / PIX;
    const int prem = p - n * PIX;
    const int oh   = prem / HWD;
    const int ow   = prem - oh * HWD;
    const char* xbase = (const char*)g_x + (size_t)n * PIX * 256;

    // ---- compute mapping: 4x4 warps, warp tile 64x32 ----
    const int m_base = (wid >> 2) * 64;
    const int n_base = (wid & 3) * 32;
    const int j   = lid >> 3;
    const int rin = lid & 7;
    const int a_lane = ((j & 1) * 8 + rin) * ROWB + (j >> 1) * 16;
    const int b_lane = ((j >> 1) * 8 + rin) * ROWB + (j & 1) * 16;
    const int erow = lid >> 2;
    const int ecol = (lid & 3) * 2;

    float acc[4][4][4];
    #pragma unroll
    for (int i = 0; i < 4; i++)
        #pragma unroll
        for (int jj = 0; jj < 4; jj++)
            #pragma unroll
            for (int q = 0; q < 4; q++) acc[i][jj][q] = 0.0f;

    auto issue = [&](int s, int slot) {
        const uint32_t stg = sb + slot * STG_B;
        const int tap = s >> 2;
        const int c0  = (s & 3) * 32;
        const int dh = tap / 3 - 1, dw = tap % 3 - 1;
        const int ih = oh + dh, iw = ow + dw;
        const bool v = ((unsigned)ih < (unsigned)HWD) && ((unsigned)iw < (unsigned)HWD);
        const uint32_t vsz = v ? 16u : 0u;
        const char* asrc = xbase + ((size_t)(v ? ih * HWD + iw : 0) * 128 + c0) * 2 + aoff;
        const uint32_t adst = stg + A_OFF + arow * ROWB + aoff;
        CP16(adst,      asrc,      vsz);
        CP16(adst + 16, asrc + 16, vsz);
        const char* bsrc = wbase + ((size_t)(s * C_OUT + oc0 + brow) * BK) * 2 + boff;
        const uint32_t bdst = stg + B_OFF + brow * ROWB + boff;
        CP16(bdst, bsrc, 16u);
        CP_COMMIT();
    };

    auto compute = [&](int slot) {
        const uint32_t stg = sb + slot * STG_B;
        const uint32_t abase = stg + A_OFF + m_base * ROWB + a_lane;
        const uint32_t bbase = stg + B_OFF + n_base * ROWB + b_lane;
        #pragma unroll
        for (int kk = 0; kk < 2; kk++) {
            uint32_t ah[4][4], bh[2][4];
            #pragma unroll
            for (int mt = 0; mt < 4; mt++)
                ldsm_x4(ah[mt], abase + mt * (16 * ROWB) + kk * 32);
            #pragma unroll
            for (int nt = 0; nt < 2; nt++)
                ldsm_x4(bh[nt], bbase + nt * (16 * ROWB) + kk * 32);
            #pragma unroll
            for (int mt = 0; mt < 4; mt++)
                #pragma unroll
                for (int n8 = 0; n8 < 4; n8++)
                    mma16816(acc[mt][n8], ah[mt], &bh[n8 >> 1][(n8 & 1) * 2]);
        }
    };

    // prologue: stages 0..3 into slots 0..3
    issue(0, 0); issue(1, 1); issue(2, 2); issue(3, 3);

    // paired stages; slot pattern period 6 = ring size; 1 barrier per 2 stages
    #pragma unroll 1
    for (int gg = 0; gg < 6; ++gg) {
        #pragma unroll
        for (int pp = 0; pp < 3; ++pp) {
            const int s = gg * 6 + pp * 2;
            if (s <= 32) CP_WAITG(2);
            else         CP_WAITG(0);
            __syncthreads();

            // ---- cold-start: kk0 fragment loads of stage s FIRST (latency head start)
            const uint32_t stg0  = sb + (pp * 2) * STG_B;
            const uint32_t abase = stg0 + A_OFF + m_base * ROWB + a_lane;
            const uint32_t bbase = stg0 + B_OFF + n_base * ROWB + b_lane;
            uint32_t ah0[4][4], bh0[2][4];
            #pragma unroll
            for (int mt = 0; mt < 4; mt++)
                ldsm_x4(ah0[mt], abase + mt * (16 * ROWB));
            #pragma unroll
            for (int nt = 0; nt < 2; nt++)
                ldsm_x4(bh0[nt], bbase + nt * (16 * ROWB));

            // issue next pair while kk0 fragments are in flight
            // slot(s+4) == slot(s-2): all its readers are before the barrier above
            if (s + 4 < NSTAGE) issue(s + 4, (pp * 2 + 4) % 6);
            if (s + 5 < NSTAGE) issue(s + 5, (pp * 2 + 5) % 6);

            // kk0 MMAs (same order as R14's compute kk=0)
            #pragma unroll
            for (int mt = 0; mt < 4; mt++)
                #pragma unroll
                for (int n8 = 0; n8 < 4; n8++)
                    mma16816(acc[mt][n8], ah0[mt], &bh0[n8 >> 1][(n8 & 1) * 2]);

            // kk1 of stage s
            {
                uint32_t ah[4][4], bh[2][4];
                #pragma unroll
                for (int mt = 0; mt < 4; mt++)
                    ldsm_x4(ah[mt], abase + mt * (16 * ROWB) + 32);
                #pragma unroll
                for (int nt = 0; nt < 2; nt++)
                    ldsm_x4(bh[nt], bbase + nt * (16 * ROWB) + 32);
                #pragma unroll
                for (int mt = 0; mt < 4; mt++)
                    #pragma unroll
                    for (int n8 = 0; n8 < 4; n8++)
                        mma16816(acc[mt][n8], ah[mt], &bh[n8 >> 1][(n8 & 1) * 2]);
            }

            compute(pp * 2 + 1);
        }
    }

    // ---- epilogue: NCHW stores ----
    #pragma unroll
    for (int mt = 0; mt < 4; mt++) {
        #pragma unroll
        for (int half = 0; half < 2; half++) {
            const int pix = bm0 + m_base + mt * 16 + erow + half * 8;
            const int nn  = pix / PIX;
            const int pr  = pix - nn * PIX;
            float* ob = out + (size_t)nn * C_OUT * PIX + pr;
            #pragma unroll
            for (int n8 = 0; n8 < 4; n8++) {
                const int oc = oc0 + n_base + n8 * 8 + ecol;
                ob[(size_t)oc * PIX]       = acc[mt][n8][half * 2];
                ob[(size_t)(oc + 1) * PIX] = acc[mt][n8][half * 2 + 1];
            }
        }
    }
}

// ==================== launch ====================
extern "C" void kernel_launch(void* const* d_in, const int* in_sizes, int n_in,
                              void* d_out, int out_size) {
    const float* x = (const float*)d_in[0];
    const float* w = (const float*)d_in[1];
    float* out = (float*)d_out;

    static int smem_set = 0;
    if (!smem_set) {
        cudaFuncSetAttribute(conv_mma, cudaFuncAttributeMaxDynamicSharedMemorySize, SMEMSZ);
        smem_set = 1;
    }

    prep_all<<<XBLOCKS + WBLOCKS, 256>>>(x, w);
    dim3 grid(M_TOTAL / MT, C_OUT / NT);   // (392, 2)
    conv_mma<<<grid, 512, SMEMSZ>>>(out);
}